// round 11
// baseline (speedup 1.0000x reference)
#include <cuda_runtime.h>
#include <math_constants.h>

#define NN   100000
#define EE   3200000
#define FIN  512
#define HID  16
#define NG   10
#define GF   160
#define LAMDA 0.001f
#define EPSN  1e-5f

#define SCAN_CHUNK 1024
#define NBLK ((NN + SCAN_CHUNK - 1) / SCAN_CHUNK)   // 98

#define FB    64                         // nodes per fused gather+stats block
#define FGRID ((NN + FB - 1) / FB)       // 1563
#define TST   65                         // transposed smem stride (conflict-free)

// ---------------- device scratch ----------------
__device__ float  g_deg[NN];
__device__ int    g_cnt[NN];
__device__ int    g_rowstart[NN];
__device__ int    g_fill[NN];
__device__ int    g_bsum[NBLK];
__device__ int    g_csr_r[EE];
__device__ float  g_h  [NN * HID];
__device__ float  g_agg[NN * HID];
__device__ float  g_s  [NN * NG];
__device__ double g_sums[2 * GF];
__device__ float  g_rsg[GF];
__device__ float  g_cvec[HID];
__device__ int    g_ctr;

// ---------------- helpers: packed f32x2 ----------------
__device__ __forceinline__ unsigned long long pack2(float a) {
    unsigned int u = __float_as_uint(a);
    unsigned long long r;
    asm("mov.b64 %0, {%1, %1};" : "=l"(r) : "r"(u));
    return r;
}
__device__ __forceinline__ void fma2(unsigned long long& acc,
                                     unsigned long long a, unsigned long long b) {
    asm("fma.rn.f32x2 %0, %1, %2, %3;" : "=l"(acc) : "l"(a), "l"(b), "l"(acc));
}

// ---------------- CSR build ----------------
__global__ void zero_cnt_kernel() {
    int i = blockIdx.x * blockDim.x + threadIdx.x;
    if (i < NN) g_cnt[i] = 0;
}

// 4 edges per thread, vectorized col read
__global__ void count_kernel(const int* __restrict__ ei) {
    int t = blockIdx.x * blockDim.x + threadIdx.x;
    if (t >= EE / 4) return;
    int4 c = __ldg(&((const int4*)(ei + EE))[t]);
    atomicAdd(&g_cnt[c.x], 1);
    atomicAdd(&g_cnt[c.y], 1);
    atomicAdd(&g_cnt[c.z], 1);
    atomicAdd(&g_cnt[c.w], 1);
}

__global__ void dinv_kernel() {
    int i = blockIdx.x * blockDim.x + threadIdx.x;
    if (i < NN) {
        int d = g_cnt[i];
        g_deg[i] = (d > 0) ? rsqrtf((float)d) : 0.0f;
    }
}

__global__ __launch_bounds__(512) void scan1_kernel() {
    __shared__ int sh[512];
    int b = blockIdx.x, t = threadIdx.x;
    int i0 = b * SCAN_CHUNK + 2 * t;
    int c0 = (i0     < NN) ? g_cnt[i0]     : 0;
    int c1 = (i0 + 1 < NN) ? g_cnt[i0 + 1] : 0;
    sh[t] = c0 + c1;
    __syncthreads();
    for (int off = 256; off > 0; off >>= 1) {
        if (t < off) sh[t] += sh[t + off];
        __syncthreads();
    }
    if (t == 0) g_bsum[b] = sh[0];
}

__global__ __launch_bounds__(512) void scan3_kernel() {
    __shared__ int sh[512];
    __shared__ int base_sh;
    int b = blockIdx.x, t = threadIdx.x;

    sh[t] = (t < b && t < NBLK) ? g_bsum[t] : 0;
    __syncthreads();
    for (int off = 256; off > 0; off >>= 1) {
        if (t < off) sh[t] += sh[t + off];
        __syncthreads();
    }
    if (t == 0) base_sh = sh[0];
    __syncthreads();
    int base = base_sh;
    __syncthreads();

    int i0 = b * SCAN_CHUNK + 2 * t;
    int c0 = (i0     < NN) ? g_cnt[i0]     : 0;
    int c1 = (i0 + 1 < NN) ? g_cnt[i0 + 1] : 0;
    int pair = c0 + c1;
    sh[t] = pair;
    __syncthreads();
    for (int off = 1; off < 512; off <<= 1) {
        int v = (t >= off) ? sh[t - off] : 0;
        __syncthreads();
        sh[t] += v;
        __syncthreads();
    }
    int ex = sh[t] - pair + base;
    if (i0 < NN) {
        g_rowstart[i0] = ex;
        g_fill[i0] = ex;
    }
    if (i0 + 1 < NN) {
        g_rowstart[i0 + 1] = ex + c0;
        g_fill[i0 + 1] = ex + c0;
    }
}

// 4 edges per thread, vectorized row+col reads
__global__ void fill_kernel(const int* __restrict__ ei) {
    int t = blockIdx.x * blockDim.x + threadIdx.x;
    if (t >= EE / 4) return;
    int4 r = __ldg(&((const int4*)ei)[t]);
    int4 c = __ldg(&((const int4*)(ei + EE))[t]);
    g_csr_r[atomicAdd(&g_fill[c.x], 1)] = r.x;
    g_csr_r[atomicAdd(&g_fill[c.y], 1)] = r.y;
    g_csr_r[atomicAdd(&g_fill[c.z], 1)] = r.z;
    g_csr_r[atomicAdd(&g_fill[c.w], 1)] = r.w;
}

// ---------------- mm0: proven R10 version (unchanged) ----------------
#define MMB 256
#define MMG ((NN + MMB - 1) / MMB)      // 391
__global__ __launch_bounds__(128, 3) void mm0_kernel(const float* __restrict__ x,
                                                     const float* __restrict__ W) {
    __shared__ __align__(16) float Ws[FIN * HID];      // 32 KB
    __shared__ __align__(16) float xs[2][MMB * 16];    // 32 KB
    int tid = threadIdx.x;
    for (int i = tid; i < FIN * HID; i += 128) Ws[i] = W[i];

    int n0 = blockIdx.x * MMB;
    int lr = tid >> 2;
    int cb = tid & 3;

    auto issue_chunk = [&](int kc, int b) {
#pragma unroll
        for (int it = 0; it < 8; it++) {
            int r = it * 32 + lr;
            int gr = n0 + r;
            if (gr >= NN) gr = NN - 1;
            const float* src = &x[(size_t)gr * FIN + kc * 16 + cb * 4];
            int blk = cb ^ ((r >> 1) & 3);
            unsigned sdst = (unsigned)__cvta_generic_to_shared(&xs[b][r * 16 + blk * 4]);
            asm volatile("cp.async.cg.shared.global [%0], [%1], 16;"
                         :: "r"(sdst), "l"(src));
        }
        asm volatile("cp.async.commit_group;");
    };

    issue_chunk(0, 0);
    issue_chunk(1, 1);

    unsigned long long accA[8], accB[8];
#pragma unroll
    for (int p = 0; p < 8; p++) { accA[p] = 0ull; accB[p] = 0ull; }

    int r0 = tid;
    int r1 = tid + 128;
    int key = (tid >> 1) & 3;

    for (int kc = 0; kc < FIN / 16; kc++) {
        if (kc < FIN / 16 - 1)
            asm volatile("cp.async.wait_group 1;");
        else
            asm volatile("cp.async.wait_group 0;");
        __syncthreads();

        const float4* base = (const float4*)&xs[kc & 1][0];
#pragma unroll
        for (int c = 0; c < 4; c++) {
            float4 va = base[r0 * 4 + (c ^ key)];
            float4 vb = base[r1 * 4 + (c ^ key)];
            float xa[4] = {va.x, va.y, va.z, va.w};
            float xb[4] = {vb.x, vb.y, vb.z, vb.w};
#pragma unroll
            for (int kk = 0; kk < 4; kk++) {
                int k = kc * 16 + c * 4 + kk;
                const ulonglong2* wp = (const ulonglong2*)&Ws[k * HID];
                ulonglong2 w01 = wp[0], w23 = wp[1], w45 = wp[2], w67 = wp[3];
                unsigned long long xpA = pack2(xa[kk]);
                unsigned long long xpB = pack2(xb[kk]);
                fma2(accA[0], xpA, w01.x); fma2(accA[1], xpA, w01.y);
                fma2(accA[2], xpA, w23.x); fma2(accA[3], xpA, w23.y);
                fma2(accA[4], xpA, w45.x); fma2(accA[5], xpA, w45.y);
                fma2(accA[6], xpA, w67.x); fma2(accA[7], xpA, w67.y);
                fma2(accB[0], xpB, w01.x); fma2(accB[1], xpB, w01.y);
                fma2(accB[2], xpB, w23.x); fma2(accB[3], xpB, w23.y);
                fma2(accB[4], xpB, w45.x); fma2(accB[5], xpB, w45.y);
                fma2(accB[6], xpB, w67.x); fma2(accB[7], xpB, w67.y);
            }
        }
        __syncthreads();
        if (kc + 2 < FIN / 16) issue_chunk(kc + 2, kc & 1);
    }

    union { unsigned long long u; float2 f; } cv;
    int nA = n0 + r0;
    if (nA < NN) {
        float dv = g_deg[nA];
        float4* o = (float4*)&g_h[(size_t)nA * HID];
#pragma unroll
        for (int q = 0; q < 4; q++) {
            float4 rr;
            cv.u = accA[2 * q];     rr.x = cv.f.x * dv; rr.y = cv.f.y * dv;
            cv.u = accA[2 * q + 1]; rr.z = cv.f.x * dv; rr.w = cv.f.y * dv;
            o[q] = rr;
        }
    }
    int nB = n0 + r1;
    if (nB < NN) {
        float dv = g_deg[nB];
        float4* o = (float4*)&g_h[(size_t)nB * HID];
#pragma unroll
        for (int q = 0; q < 4; q++) {
            float4 rr;
            cv.u = accB[2 * q];     rr.x = cv.f.x * dv; rr.y = cv.f.y * dv;
            cv.u = accB[2 * q + 1]; rr.z = cv.f.x * dv; rr.w = cv.f.y * dv;
            o[q] = rr;
        }
    }
}

// ---------------- fused gather + stats + embedded finalize ----------------
// 64 nodes/block, 256 threads (8 warps). Warp w gathers nodes w*8..w*8+7
// sequentially (same inner loop as the proven gather). agg goes to gmem AND
// transposed smem [feature][node] (stride 65, conflict-free). Softmax by
// threads 0..63; channel partial sums by all 8 warps (20 pairs each) with
// shuffle reduction; decoupled last-block finalize.
__global__ __launch_bounds__(256) void gstats_kernel(const float* __restrict__ L,
                                                     const float* __restrict__ gamma,
                                                     const float* __restrict__ beta) {
    __shared__ float Ls[HID * NG];
    __shared__ float xs[HID * TST];   // [f][node]
    __shared__ float ss[NG * TST];    // [g][node]
    __shared__ float tsh[GF];
    __shared__ int is_last;
    int tid  = threadIdx.x;
    int wid  = tid >> 5;
    int lane = tid & 31;
    if (tid < HID * NG) Ls[tid] = L[tid];

    int nbase = blockIdx.x * FB;
    const float4* h4 = (const float4*)g_h;
    int p = lane & 3;

    // ---- phase 1: gather (warp-per-node, 8 nodes per warp) ----
    for (int i = 0; i < 8; i++) {
        int node = nbase + wid * 8 + i;
        bool valid = node < NN;
        int s = valid ? g_rowstart[node] : 0;
        int e = valid ? (s + g_cnt[node]) : 0;
        int j = s + (lane >> 2);

        float4 a0 = make_float4(0.f, 0.f, 0.f, 0.f);
        float4 a1 = make_float4(0.f, 0.f, 0.f, 0.f);
        while (j < e - 8) {
            int r0 = __ldg(&g_csr_r[j]);
            int r1 = __ldg(&g_csr_r[j + 8]);
            float4 v0 = __ldg(&h4[(size_t)r0 * 4 + p]);
            float4 v1 = __ldg(&h4[(size_t)r1 * 4 + p]);
            a0.x += v0.x; a0.y += v0.y; a0.z += v0.z; a0.w += v0.w;
            a1.x += v1.x; a1.y += v1.y; a1.z += v1.z; a1.w += v1.w;
            j += 16;
        }
        if (j < e) {
            int r0 = __ldg(&g_csr_r[j]);
            float4 v0 = __ldg(&h4[(size_t)r0 * 4 + p]);
            a0.x += v0.x; a0.y += v0.y; a0.z += v0.z; a0.w += v0.w;
        }
        a0.x += a1.x; a0.y += a1.y; a0.z += a1.z; a0.w += a1.w;
#pragma unroll
        for (int m = 16; m >= 4; m >>= 1) {
            a0.x += __shfl_xor_sync(0xffffffff, a0.x, m);
            a0.y += __shfl_xor_sync(0xffffffff, a0.y, m);
            a0.z += __shfl_xor_sync(0xffffffff, a0.z, m);
            a0.w += __shfl_xor_sync(0xffffffff, a0.w, m);
        }
        if (lane < 4) {
            float dc = valid ? g_deg[node] : 0.0f;
            a0.x *= dc; a0.y *= dc; a0.z *= dc; a0.w *= dc;
            if (valid)
                ((float4*)g_agg)[(size_t)node * 4 + lane] = a0;
            int nl = wid * 8 + i;
            xs[(p * 4 + 0) * TST + nl] = a0.x;
            xs[(p * 4 + 1) * TST + nl] = a0.y;
            xs[(p * 4 + 2) * TST + nl] = a0.z;
            xs[(p * 4 + 3) * TST + nl] = a0.w;
        }
    }
    __syncthreads();

    // ---- phase 2: softmax (threads 0..63, one node each) ----
    if (tid < FB) {
        int node = nbase + tid;
        if (node < NN) {
            float xr[HID];
#pragma unroll
            for (int k = 0; k < HID; k++) xr[k] = xs[k * TST + tid];
            float logit[NG];
#pragma unroll
            for (int g = 0; g < NG; g++) logit[g] = 0.0f;
#pragma unroll
            for (int k = 0; k < HID; k++)
#pragma unroll
                for (int g = 0; g < NG; g++) logit[g] += xr[k] * Ls[k * NG + g];
            float m = -CUDART_INF_F;
#pragma unroll
            for (int g = 0; g < NG; g++) m = fmaxf(m, logit[g]);
            float sum = 0.0f;
            float sv[NG];
#pragma unroll
            for (int g = 0; g < NG; g++) { sv[g] = __expf(logit[g] - m); sum += sv[g]; }
            float inv = 1.0f / sum;
#pragma unroll
            for (int g = 0; g < NG; g++) {
                sv[g] *= inv;
                ss[g * TST + tid] = sv[g];
                g_s[(size_t)node * NG + g] = sv[g];
            }
        } else {
#pragma unroll
            for (int g = 0; g < NG; g++) ss[g * TST + tid] = 0.0f;
        }
    }
    __syncthreads();

    // ---- phase 3: channel partial sums, all 8 warps (20 pairs each) ----
#pragma unroll
    for (int q = 0; q < 20; q++) {
        int pp = wid * 20 + q;
        int g = pp >> 4;
        int f = pp & 15;
        float a1 = 0.0f, a2 = 0.0f;
#pragma unroll
        for (int jj = lane; jj < FB; jj += 32) {
            float t = ss[g * TST + jj] * xs[f * TST + jj];
            a1 += t;
            a2 += t * t;
        }
#pragma unroll
        for (int m = 16; m >= 1; m >>= 1) {
            a1 += __shfl_xor_sync(0xffffffff, a1, m);
            a2 += __shfl_xor_sync(0xffffffff, a2, m);
        }
        if (lane == 0) {
            atomicAdd(&g_sums[pp], (double)a1);
            atomicAdd(&g_sums[GF + pp], (double)a2);
        }
    }

    // ---- phase 4: decoupled last-block finalize ----
    __threadfence();
    if (tid == 0) {
        int old = atomicAdd(&g_ctr, 1);
        is_last = (old == (int)gridDim.x - 1) ? 1 : 0;
    }
    __syncthreads();
    if (is_last) {
        if (tid < GF) {
            double s1 = g_sums[tid];
            double s2 = g_sums[GF + tid];
            g_sums[tid] = 0.0;
            g_sums[GF + tid] = 0.0;
            double mean = s1 / (double)NN;
            double var  = s2 / (double)NN - mean * mean;
            float v = (float)var;
            if (v < 0.0f) v = 0.0f;
            float rs = rsqrtf(v + EPSN);
            float rg = rs * gamma[tid];
            g_rsg[tid] = rg;
            tsh[tid] = beta[tid] - (float)mean * rg;
        }
        __syncthreads();
        if (tid < HID) {
            float cf = 0.0f;
#pragma unroll
            for (int g = 0; g < NG; g++) cf += tsh[g * HID + tid];
            g_cvec[tid] = cf;
        }
        if (tid == 0) g_ctr = 0;
    }
}

// ---------------- apply + fused next-layer mm16 ----------------
__global__ __launch_bounds__(256) void apply_mm_kernel(const float* __restrict__ Wn) {
    __shared__ float rg[GF];
    __shared__ float cs[HID];
    __shared__ float Ws[HID * HID];
    int tid = threadIdx.x;
    if (tid < GF) rg[tid] = g_rsg[tid];
    if (tid < HID) cs[tid] = g_cvec[tid];
    if (tid < HID * HID) Ws[tid] = Wn[tid];
    __syncthreads();

    int nIdx = blockIdx.x * 256 + tid;
    if (nIdx >= NN) return;

    float sv[NG];
#pragma unroll
    for (int g = 0; g < NG; g++) sv[g] = g_s[(size_t)nIdx * NG + g];

    float xr[HID];
    const float4* xi = (const float4*)&g_agg[(size_t)nIdx * HID];
#pragma unroll
    for (int q = 0; q < 4; q++) {
        float4 v = xi[q];
        xr[q * 4 + 0] = v.x; xr[q * 4 + 1] = v.y; xr[q * 4 + 2] = v.z; xr[q * 4 + 3] = v.w;
    }

    float res[HID];
#pragma unroll
    for (int f = 0; f < HID; f++) {
        float a = 0.0f;
#pragma unroll
        for (int g = 0; g < NG; g++) a += sv[g] * rg[g * HID + f];
        float v = xr[f] + LAMDA * (xr[f] * a + cs[f]);
        res[f] = fmaxf(v, 0.0f);
    }

    float acc[HID];
#pragma unroll
    for (int f = 0; f < HID; f++) acc[f] = 0.0f;
#pragma unroll
    for (int k = 0; k < HID; k++)
#pragma unroll
        for (int f = 0; f < HID; f++) acc[f] += res[k] * Ws[k * HID + f];

    float dv = g_deg[nIdx];
    float4* o = (float4*)&g_h[(size_t)nIdx * HID];
#pragma unroll
    for (int q = 0; q < 4; q++)
        o[q] = make_float4(acc[q * 4 + 0] * dv, acc[q * 4 + 1] * dv,
                           acc[q * 4 + 2] * dv, acc[q * 4 + 3] * dv);
}

// ---------------- final apply (layer 2): write output ----------------
__global__ __launch_bounds__(256) void apply_out_kernel(float* __restrict__ out) {
    __shared__ float rg[GF];
    __shared__ float cs[HID];
    int tid = threadIdx.x;
    if (tid < GF) rg[tid] = g_rsg[tid];
    if (tid < HID) cs[tid] = g_cvec[tid];
    __syncthreads();

    int nIdx = blockIdx.x * 256 + tid;
    if (nIdx >= NN) return;

    float sv[NG];
#pragma unroll
    for (int g = 0; g < NG; g++) sv[g] = g_s[(size_t)nIdx * NG + g];

    float xr[HID];
    const float4* xi = (const float4*)&g_agg[(size_t)nIdx * HID];
#pragma unroll
    for (int q = 0; q < 4; q++) {
        float4 v = xi[q];
        xr[q * 4 + 0] = v.x; xr[q * 4 + 1] = v.y; xr[q * 4 + 2] = v.z; xr[q * 4 + 3] = v.w;
    }

    float res[HID];
#pragma unroll
    for (int f = 0; f < HID; f++) {
        float a = 0.0f;
#pragma unroll
        for (int g = 0; g < NG; g++) a += sv[g] * rg[g * HID + f];
        float v = xr[f] + LAMDA * (xr[f] * a + cs[f]);
        res[f] = fmaxf(v, 0.0f);
    }

    float4* o = (float4*)&out[(size_t)nIdx * HID];
#pragma unroll
    for (int q = 0; q < 4; q++)
        o[q] = make_float4(res[q * 4 + 0], res[q * 4 + 1], res[q * 4 + 2], res[q * 4 + 3]);
}

// ---------------- launcher ----------------
extern "C" void kernel_launch(void* const* d_in, const int* in_sizes, int n_in,
                              void* d_out, int out_size) {
    const float* x  = (const float*)d_in[0];
    const int*   ei = (const int*)d_in[1];
    const float* W[3] = {(const float*)d_in[2], (const float*)d_in[3], (const float*)d_in[4]};
    const float* L[3] = {(const float*)d_in[5], (const float*)d_in[6], (const float*)d_in[7]};
    const float* gm[3] = {(const float*)d_in[8], (const float*)d_in[9], (const float*)d_in[10]};
    const float* bt[3] = {(const float*)d_in[11], (const float*)d_in[12], (const float*)d_in[13]};
    float* out = (float*)d_out;

    const int TB = 256;
    zero_cnt_kernel<<<(NN + TB - 1) / TB, TB>>>();        // 1
    count_kernel<<<(EE / 4 + TB - 1) / TB, TB>>>(ei);     // 2
    dinv_kernel<<<(NN + TB - 1) / TB, TB>>>();            // 3
    mm0_kernel<<<MMG, 128>>>(x, W[0]);                    // 4  <- profiled slot
    scan1_kernel<<<NBLK, 512>>>();                        // 5
    scan3_kernel<<<NBLK, 512>>>();                        // 6
    fill_kernel<<<(EE / 4 + TB - 1) / TB, TB>>>(ei);      // 7

    for (int i = 0; i < 3; i++) {
        gstats_kernel<<<FGRID, 256>>>(L[i], gm[i], bt[i]);
        if (i < 2)
            apply_mm_kernel<<<(NN + 255) / 256, 256>>>(W[i + 1]);
        else
            apply_out_kernel<<<(NN + 255) / 256, 256>>>(out);
    }
}

// round 12
// speedup vs baseline: 1.6545x; 1.6545x over previous
#include <cuda_runtime.h>
#include <math_constants.h>

#define NN   100000
#define EE   3200000
#define FIN  512
#define HID  16
#define NG   10
#define GF   160
#define LAMDA 0.001f
#define EPSN  1e-5f

#define SCAN_CHUNK 1024
#define NBLK ((NN + SCAN_CHUNK - 1) / SCAN_CHUNK)   // 98

// ---------------- device scratch ----------------
__device__ float  g_deg[NN];
__device__ int    g_cnt[NN];
__device__ int    g_rowstart[NN];
__device__ int    g_fill[NN];
__device__ int    g_bsum[NBLK];
__device__ int    g_csr_r[EE];
__device__ float  g_h  [NN * HID];
__device__ float  g_agg[NN * HID];
__device__ float  g_s  [NN * NG];
__device__ double g_sums[2 * GF];
__device__ float  g_rsg[GF];
__device__ float  g_cvec[HID];
__device__ int    g_ctr;

// ---------------- helpers: packed f32x2 ----------------
__device__ __forceinline__ unsigned long long pack2(float a) {
    unsigned int u = __float_as_uint(a);
    unsigned long long r;
    asm("mov.b64 %0, {%1, %1};" : "=l"(r) : "r"(u));
    return r;
}
__device__ __forceinline__ void fma2(unsigned long long& acc,
                                     unsigned long long a, unsigned long long b) {
    asm("fma.rn.f32x2 %0, %1, %2, %3;" : "=l"(acc) : "l"(a), "l"(b), "l"(acc));
}

// ---------------- CSR build ----------------
__global__ void zero_cnt_kernel() {
    int i = blockIdx.x * blockDim.x + threadIdx.x;
    if (i < NN) g_cnt[i] = 0;
}

// proven scalar version
__global__ void count_kernel(const int* __restrict__ ei) {
    int e = blockIdx.x * blockDim.x + threadIdx.x;
    if (e < EE) atomicAdd(&g_cnt[__ldg(&ei[EE + e])], 1);
}

// scan1 + fused dinv (reads g_cnt anyway)
__global__ __launch_bounds__(512) void scan1_kernel() {
    __shared__ int sh[512];
    int b = blockIdx.x, t = threadIdx.x;
    int i0 = b * SCAN_CHUNK + 2 * t;
    int c0 = (i0     < NN) ? g_cnt[i0]     : 0;
    int c1 = (i0 + 1 < NN) ? g_cnt[i0 + 1] : 0;
    if (i0     < NN) g_deg[i0]     = (c0 > 0) ? rsqrtf((float)c0) : 0.0f;
    if (i0 + 1 < NN) g_deg[i0 + 1] = (c1 > 0) ? rsqrtf((float)c1) : 0.0f;
    sh[t] = c0 + c1;
    __syncthreads();
    for (int off = 256; off > 0; off >>= 1) {
        if (t < off) sh[t] += sh[t + off];
        __syncthreads();
    }
    if (t == 0) g_bsum[b] = sh[0];
}

__global__ __launch_bounds__(512) void scan3_kernel() {
    __shared__ int sh[512];
    __shared__ int base_sh;
    int b = blockIdx.x, t = threadIdx.x;

    sh[t] = (t < b && t < NBLK) ? g_bsum[t] : 0;
    __syncthreads();
    for (int off = 256; off > 0; off >>= 1) {
        if (t < off) sh[t] += sh[t + off];
        __syncthreads();
    }
    if (t == 0) base_sh = sh[0];
    __syncthreads();
    int base = base_sh;
    __syncthreads();

    int i0 = b * SCAN_CHUNK + 2 * t;
    int c0 = (i0     < NN) ? g_cnt[i0]     : 0;
    int c1 = (i0 + 1 < NN) ? g_cnt[i0 + 1] : 0;
    int pair = c0 + c1;
    sh[t] = pair;
    __syncthreads();
    for (int off = 1; off < 512; off <<= 1) {
        int v = (t >= off) ? sh[t - off] : 0;
        __syncthreads();
        sh[t] += v;
        __syncthreads();
    }
    int ex = sh[t] - pair + base;
    if (i0 < NN) {
        g_rowstart[i0] = ex;
        g_fill[i0] = ex;
    }
    if (i0 + 1 < NN) {
        g_rowstart[i0 + 1] = ex + c0;
        g_fill[i0 + 1] = ex + c0;
    }
}

// proven scalar version
__global__ void fill_kernel(const int* __restrict__ ei) {
    int e = blockIdx.x * blockDim.x + threadIdx.x;
    if (e >= EE) return;
    int r = __ldg(&ei[e]);
    int c = __ldg(&ei[EE + e]);
    int pos = atomicAdd(&g_fill[c], 1);
    g_csr_r[pos] = r;
}

// ---------------- mm0: proven R10 version (unchanged) ----------------
#define MMB 256
#define MMG ((NN + MMB - 1) / MMB)      // 391
__global__ __launch_bounds__(128, 3) void mm0_kernel(const float* __restrict__ x,
                                                     const float* __restrict__ W) {
    __shared__ __align__(16) float Ws[FIN * HID];      // 32 KB
    __shared__ __align__(16) float xs[2][MMB * 16];    // 32 KB
    int tid = threadIdx.x;
    for (int i = tid; i < FIN * HID; i += 128) Ws[i] = W[i];

    int n0 = blockIdx.x * MMB;
    int lr = tid >> 2;
    int cb = tid & 3;

    auto issue_chunk = [&](int kc, int b) {
#pragma unroll
        for (int it = 0; it < 8; it++) {
            int r = it * 32 + lr;
            int gr = n0 + r;
            if (gr >= NN) gr = NN - 1;
            const float* src = &x[(size_t)gr * FIN + kc * 16 + cb * 4];
            int blk = cb ^ ((r >> 1) & 3);
            unsigned sdst = (unsigned)__cvta_generic_to_shared(&xs[b][r * 16 + blk * 4]);
            asm volatile("cp.async.cg.shared.global [%0], [%1], 16;"
                         :: "r"(sdst), "l"(src));
        }
        asm volatile("cp.async.commit_group;");
    };

    issue_chunk(0, 0);
    issue_chunk(1, 1);

    unsigned long long accA[8], accB[8];
#pragma unroll
    for (int p = 0; p < 8; p++) { accA[p] = 0ull; accB[p] = 0ull; }

    int r0 = tid;
    int r1 = tid + 128;
    int key = (tid >> 1) & 3;

    for (int kc = 0; kc < FIN / 16; kc++) {
        if (kc < FIN / 16 - 1)
            asm volatile("cp.async.wait_group 1;");
        else
            asm volatile("cp.async.wait_group 0;");
        __syncthreads();

        const float4* base = (const float4*)&xs[kc & 1][0];
#pragma unroll
        for (int c = 0; c < 4; c++) {
            float4 va = base[r0 * 4 + (c ^ key)];
            float4 vb = base[r1 * 4 + (c ^ key)];
            float xa[4] = {va.x, va.y, va.z, va.w};
            float xb[4] = {vb.x, vb.y, vb.z, vb.w};
#pragma unroll
            for (int kk = 0; kk < 4; kk++) {
                int k = kc * 16 + c * 4 + kk;
                const ulonglong2* wp = (const ulonglong2*)&Ws[k * HID];
                ulonglong2 w01 = wp[0], w23 = wp[1], w45 = wp[2], w67 = wp[3];
                unsigned long long xpA = pack2(xa[kk]);
                unsigned long long xpB = pack2(xb[kk]);
                fma2(accA[0], xpA, w01.x); fma2(accA[1], xpA, w01.y);
                fma2(accA[2], xpA, w23.x); fma2(accA[3], xpA, w23.y);
                fma2(accA[4], xpA, w45.x); fma2(accA[5], xpA, w45.y);
                fma2(accA[6], xpA, w67.x); fma2(accA[7], xpA, w67.y);
                fma2(accB[0], xpB, w01.x); fma2(accB[1], xpB, w01.y);
                fma2(accB[2], xpB, w23.x); fma2(accB[3], xpB, w23.y);
                fma2(accB[4], xpB, w45.x); fma2(accB[5], xpB, w45.y);
                fma2(accB[6], xpB, w67.x); fma2(accB[7], xpB, w67.y);
            }
        }
        __syncthreads();
        if (kc + 2 < FIN / 16) issue_chunk(kc + 2, kc & 1);
    }

    union { unsigned long long u; float2 f; } cv;
    int nA = n0 + r0;
    if (nA < NN) {
        float dv = g_deg[nA];
        float4* o = (float4*)&g_h[(size_t)nA * HID];
#pragma unroll
        for (int q = 0; q < 4; q++) {
            float4 rr;
            cv.u = accA[2 * q];     rr.x = cv.f.x * dv; rr.y = cv.f.y * dv;
            cv.u = accA[2 * q + 1]; rr.z = cv.f.x * dv; rr.w = cv.f.y * dv;
            o[q] = rr;
        }
    }
    int nB = n0 + r1;
    if (nB < NN) {
        float dv = g_deg[nB];
        float4* o = (float4*)&g_h[(size_t)nB * HID];
#pragma unroll
        for (int q = 0; q < 4; q++) {
            float4 rr;
            cv.u = accB[2 * q];     rr.x = cv.f.x * dv; rr.y = cv.f.y * dv;
            cv.u = accB[2 * q + 1]; rr.z = cv.f.x * dv; rr.w = cv.f.y * dv;
            o[q] = rr;
        }
    }
}

// ---------------- gather: warp per node, 4 lanes/edge, 2-way unroll (proven) ----------------
__global__ __launch_bounds__(256) void gather_kernel() {
    int node = blockIdx.x * 8 + (threadIdx.x >> 5);
    if (node >= NN) return;
    int lane = threadIdx.x & 31;
    int p = lane & 3;

    int s = g_rowstart[node];
    int e = s + g_cnt[node];
    int j = s + (lane >> 2);

    float4 a0 = make_float4(0.f, 0.f, 0.f, 0.f);
    float4 a1 = make_float4(0.f, 0.f, 0.f, 0.f);
    const float4* h4 = (const float4*)g_h;

    while (j < e - 8) {
        int r0 = __ldg(&g_csr_r[j]);
        int r1 = __ldg(&g_csr_r[j + 8]);
        float4 v0 = __ldg(&h4[(size_t)r0 * 4 + p]);
        float4 v1 = __ldg(&h4[(size_t)r1 * 4 + p]);
        a0.x += v0.x; a0.y += v0.y; a0.z += v0.z; a0.w += v0.w;
        a1.x += v1.x; a1.y += v1.y; a1.z += v1.z; a1.w += v1.w;
        j += 16;
    }
    if (j < e) {
        int r0 = __ldg(&g_csr_r[j]);
        float4 v0 = __ldg(&h4[(size_t)r0 * 4 + p]);
        a0.x += v0.x; a0.y += v0.y; a0.z += v0.z; a0.w += v0.w;
    }
    a0.x += a1.x; a0.y += a1.y; a0.z += a1.z; a0.w += a1.w;

#pragma unroll
    for (int m = 16; m >= 4; m >>= 1) {
        a0.x += __shfl_xor_sync(0xffffffff, a0.x, m);
        a0.y += __shfl_xor_sync(0xffffffff, a0.y, m);
        a0.z += __shfl_xor_sync(0xffffffff, a0.z, m);
        a0.w += __shfl_xor_sync(0xffffffff, a0.w, m);
    }
    if (lane < 4) {
        float dc = g_deg[node];
        a0.x *= dc; a0.y *= dc; a0.z *= dc; a0.w *= dc;
        ((float4*)g_agg)[(size_t)node * 4 + lane] = a0;
    }
}

// ---------------- stats + embedded finalize (decoupled last-block, proven) ----------------
__global__ __launch_bounds__(256) void stats_kernel(const float* __restrict__ L,
                                                    const float* __restrict__ gamma,
                                                    const float* __restrict__ beta) {
    __shared__ float Ls[HID * NG];
    __shared__ float xs[256 * HID];
    __shared__ float ss[256 * NG];
    __shared__ float tsh[GF];
    __shared__ int is_last;
    int tid = threadIdx.x;
    if (tid < HID * NG) Ls[tid] = L[tid];
    __syncthreads();

    int nIdx = blockIdx.x * 256 + tid;
    float xr[HID];
    float sv[NG];
#pragma unroll
    for (int k = 0; k < HID; k++) xr[k] = 0.0f;
#pragma unroll
    for (int g = 0; g < NG; g++) sv[g] = 0.0f;

    if (nIdx < NN) {
        const float4* xi = (const float4*)&g_agg[(size_t)nIdx * HID];
#pragma unroll
        for (int q = 0; q < 4; q++) {
            float4 v = xi[q];
            xr[q * 4 + 0] = v.x; xr[q * 4 + 1] = v.y; xr[q * 4 + 2] = v.z; xr[q * 4 + 3] = v.w;
        }
        float logit[NG];
#pragma unroll
        for (int g = 0; g < NG; g++) logit[g] = 0.0f;
#pragma unroll
        for (int k = 0; k < HID; k++)
#pragma unroll
            for (int g = 0; g < NG; g++) logit[g] += xr[k] * Ls[k * NG + g];
        float m = -CUDART_INF_F;
#pragma unroll
        for (int g = 0; g < NG; g++) m = fmaxf(m, logit[g]);
        float sum = 0.0f;
#pragma unroll
        for (int g = 0; g < NG; g++) { sv[g] = __expf(logit[g] - m); sum += sv[g]; }
        float inv = 1.0f / sum;
#pragma unroll
        for (int g = 0; g < NG; g++) sv[g] *= inv;
#pragma unroll
        for (int g = 0; g < NG; g++) g_s[(size_t)nIdx * NG + g] = sv[g];
    }

    {
        float4* xw = (float4*)&xs[tid * HID];
#pragma unroll
        for (int q = 0; q < 4; q++)
            xw[q] = make_float4(xr[q * 4 + 0], xr[q * 4 + 1], xr[q * 4 + 2], xr[q * 4 + 3]);
#pragma unroll
        for (int g = 0; g < NG; g++) ss[tid * NG + g] = sv[g];
    }
    __syncthreads();

    if (tid < GF) {
        int g = tid >> 4;
        int f = tid & 15;
        float a1 = 0.0f, a2 = 0.0f;
        for (int jj = 0; jj < 256; jj++) {
            float t = ss[jj * NG + g] * xs[jj * HID + f];
            a1 += t;
            a2 += t * t;
        }
        atomicAdd(&g_sums[tid], (double)a1);
        atomicAdd(&g_sums[GF + tid], (double)a2);
    }

    __threadfence();
    if (tid == 0) {
        int old = atomicAdd(&g_ctr, 1);
        is_last = (old == (int)gridDim.x - 1) ? 1 : 0;
    }
    __syncthreads();
    if (is_last) {
        if (tid < GF) {
            double s1 = g_sums[tid];
            double s2 = g_sums[GF + tid];
            g_sums[tid] = 0.0;
            g_sums[GF + tid] = 0.0;
            double mean = s1 / (double)NN;
            double var  = s2 / (double)NN - mean * mean;
            float v = (float)var;
            if (v < 0.0f) v = 0.0f;
            float rs = rsqrtf(v + EPSN);
            float rg = rs * gamma[tid];
            g_rsg[tid] = rg;
            tsh[tid] = beta[tid] - (float)mean * rg;
        }
        __syncthreads();
        if (tid < HID) {
            float cf = 0.0f;
#pragma unroll
            for (int g = 0; g < NG; g++) cf += tsh[g * HID + tid];
            g_cvec[tid] = cf;
        }
        if (tid == 0) g_ctr = 0;
    }
}

// ---------------- apply + fused next-layer mm16 ----------------
__global__ __launch_bounds__(256) void apply_mm_kernel(const float* __restrict__ Wn) {
    __shared__ float rg[GF];
    __shared__ float cs[HID];
    __shared__ float Ws[HID * HID];
    int tid = threadIdx.x;
    if (tid < GF) rg[tid] = g_rsg[tid];
    if (tid < HID) cs[tid] = g_cvec[tid];
    if (tid < HID * HID) Ws[tid] = Wn[tid];
    __syncthreads();

    int nIdx = blockIdx.x * 256 + tid;
    if (nIdx >= NN) return;

    float sv[NG];
#pragma unroll
    for (int g = 0; g < NG; g++) sv[g] = g_s[(size_t)nIdx * NG + g];

    float xr[HID];
    const float4* xi = (const float4*)&g_agg[(size_t)nIdx * HID];
#pragma unroll
    for (int q = 0; q < 4; q++) {
        float4 v = xi[q];
        xr[q * 4 + 0] = v.x; xr[q * 4 + 1] = v.y; xr[q * 4 + 2] = v.z; xr[q * 4 + 3] = v.w;
    }

    float res[HID];
#pragma unroll
    for (int f = 0; f < HID; f++) {
        float a = 0.0f;
#pragma unroll
        for (int g = 0; g < NG; g++) a += sv[g] * rg[g * HID + f];
        float v = xr[f] + LAMDA * (xr[f] * a + cs[f]);
        res[f] = fmaxf(v, 0.0f);
    }

    float acc[HID];
#pragma unroll
    for (int f = 0; f < HID; f++) acc[f] = 0.0f;
#pragma unroll
    for (int k = 0; k < HID; k++)
#pragma unroll
        for (int f = 0; f < HID; f++) acc[f] += res[k] * Ws[k * HID + f];

    float dv = g_deg[nIdx];
    float4* o = (float4*)&g_h[(size_t)nIdx * HID];
#pragma unroll
    for (int q = 0; q < 4; q++)
        o[q] = make_float4(acc[q * 4 + 0] * dv, acc[q * 4 + 1] * dv,
                           acc[q * 4 + 2] * dv, acc[q * 4 + 3] * dv);
}

// ---------------- final apply (layer 2): write output ----------------
__global__ __launch_bounds__(256) void apply_out_kernel(float* __restrict__ out) {
    __shared__ float rg[GF];
    __shared__ float cs[HID];
    int tid = threadIdx.x;
    if (tid < GF) rg[tid] = g_rsg[tid];
    if (tid < HID) cs[tid] = g_cvec[tid];
    __syncthreads();

    int nIdx = blockIdx.x * 256 + tid;
    if (nIdx >= NN) return;

    float sv[NG];
#pragma unroll
    for (int g = 0; g < NG; g++) sv[g] = g_s[(size_t)nIdx * NG + g];

    float xr[HID];
    const float4* xi = (const float4*)&g_agg[(size_t)nIdx * HID];
#pragma unroll
    for (int q = 0; q < 4; q++) {
        float4 v = xi[q];
        xr[q * 4 + 0] = v.x; xr[q * 4 + 1] = v.y; xr[q * 4 + 2] = v.z; xr[q * 4 + 3] = v.w;
    }

    float res[HID];
#pragma unroll
    for (int f = 0; f < HID; f++) {
        float a = 0.0f;
#pragma unroll
        for (int g = 0; g < NG; g++) a += sv[g] * rg[g * HID + f];
        float v = xr[f] + LAMDA * (xr[f] * a + cs[f]);
        res[f] = fmaxf(v, 0.0f);
    }

    float4* o = (float4*)&out[(size_t)nIdx * HID];
#pragma unroll
    for (int q = 0; q < 4; q++)
        o[q] = make_float4(res[q * 4 + 0], res[q * 4 + 1], res[q * 4 + 2], res[q * 4 + 3]);
}

// ---------------- launcher ----------------
extern "C" void kernel_launch(void* const* d_in, const int* in_sizes, int n_in,
                              void* d_out, int out_size) {
    const float* x  = (const float*)d_in[0];
    const int*   ei = (const int*)d_in[1];
    const float* W[3] = {(const float*)d_in[2], (const float*)d_in[3], (const float*)d_in[4]};
    const float* L[3] = {(const float*)d_in[5], (const float*)d_in[6], (const float*)d_in[7]};
    const float* gm[3] = {(const float*)d_in[8], (const float*)d_in[9], (const float*)d_in[10]};
    const float* bt[3] = {(const float*)d_in[11], (const float*)d_in[12], (const float*)d_in[13]};
    float* out = (float*)d_out;

    const int TB = 256;
    zero_cnt_kernel<<<(NN + TB - 1) / TB, TB>>>();        // 1
    count_kernel<<<(EE + TB - 1) / TB, TB>>>(ei);         // 2
    scan1_kernel<<<NBLK, 512>>>();                        // 3 (+dinv fused)
    mm0_kernel<<<MMG, 128>>>(x, W[0]);                    // 4  <- profiled slot
    scan3_kernel<<<NBLK, 512>>>();                        // 5
    fill_kernel<<<(EE + TB - 1) / TB, TB>>>(ei);          // 6

    for (int i = 0; i < 3; i++) {
        gather_kernel<<<(NN + 7) / 8, 256>>>();
        stats_kernel<<<(NN + 255) / 256, 256>>>(L[i], gm[i], bt[i]);
        if (i < 2)
            apply_mm_kernel<<<(NN + 255) / 256, 256>>>(W[i + 1]);
        else
            apply_out_kernel<<<(NN + 255) / 256, 256>>>(out);
    }
}

// round 13
// speedup vs baseline: 1.6691x; 1.0088x over previous
#include <cuda_runtime.h>
#include <math_constants.h>

#define NN   100000
#define EE   3200000
#define FIN  512
#define HID  16
#define NG   10
#define GF   160
#define LAMDA 0.001f
#define EPSN  1e-5f

#define SCAN_CHUNK 1024
#define NBLK ((NN + SCAN_CHUNK - 1) / SCAN_CHUNK)   // 98

// ---------------- device scratch ----------------
__device__ float  g_deg[NN];
__device__ int    g_cnt[NN];
__device__ int    g_rowstart[NN];
__device__ int    g_fill[NN];
__device__ int    g_bsum[NBLK];
__device__ int    g_csr_r[EE];
__device__ float  g_h  [NN * HID];
__device__ float  g_agg[NN * HID];
__device__ double g_sums[2 * GF];
__device__ float  g_rsg[GF];
__device__ float  g_cvec[HID];
__device__ int    g_ctr;
__device__ int    g_ctr2;
__device__ volatile int g_flag;

// ---------------- helpers: packed f32x2 ----------------
__device__ __forceinline__ unsigned long long pack2(float a) {
    unsigned int u = __float_as_uint(a);
    unsigned long long r;
    asm("mov.b64 %0, {%1, %1};" : "=l"(r) : "r"(u));
    return r;
}
__device__ __forceinline__ void fma2(unsigned long long& acc,
                                     unsigned long long a, unsigned long long b) {
    asm("fma.rn.f32x2 %0, %1, %2, %3;" : "=l"(acc) : "l"(a), "l"(b), "l"(acc));
}

// ---------------- CSR build ----------------
__global__ void zero_cnt_kernel() {
    int i = blockIdx.x * blockDim.x + threadIdx.x;
    if (i < NN) g_cnt[i] = 0;
}

__global__ void count_kernel(const int* __restrict__ ei) {
    int e = blockIdx.x * blockDim.x + threadIdx.x;
    if (e < EE) atomicAdd(&g_cnt[__ldg(&ei[EE + e])], 1);
}

// scan1 + fused dinv
__global__ __launch_bounds__(512) void scan1_kernel() {
    __shared__ int sh[512];
    int b = blockIdx.x, t = threadIdx.x;
    int i0 = b * SCAN_CHUNK + 2 * t;
    int c0 = (i0     < NN) ? g_cnt[i0]     : 0;
    int c1 = (i0 + 1 < NN) ? g_cnt[i0 + 1] : 0;
    if (i0     < NN) g_deg[i0]     = (c0 > 0) ? rsqrtf((float)c0) : 0.0f;
    if (i0 + 1 < NN) g_deg[i0 + 1] = (c1 > 0) ? rsqrtf((float)c1) : 0.0f;
    sh[t] = c0 + c1;
    __syncthreads();
    for (int off = 256; off > 0; off >>= 1) {
        if (t < off) sh[t] += sh[t + off];
        __syncthreads();
    }
    if (t == 0) g_bsum[b] = sh[0];
}

__global__ __launch_bounds__(512) void scan3_kernel() {
    __shared__ int sh[512];
    __shared__ int base_sh;
    int b = blockIdx.x, t = threadIdx.x;

    sh[t] = (t < b && t < NBLK) ? g_bsum[t] : 0;
    __syncthreads();
    for (int off = 256; off > 0; off >>= 1) {
        if (t < off) sh[t] += sh[t + off];
        __syncthreads();
    }
    if (t == 0) base_sh = sh[0];
    __syncthreads();
    int base = base_sh;
    __syncthreads();

    int i0 = b * SCAN_CHUNK + 2 * t;
    int c0 = (i0     < NN) ? g_cnt[i0]     : 0;
    int c1 = (i0 + 1 < NN) ? g_cnt[i0 + 1] : 0;
    int pair = c0 + c1;
    sh[t] = pair;
    __syncthreads();
    for (int off = 1; off < 512; off <<= 1) {
        int v = (t >= off) ? sh[t - off] : 0;
        __syncthreads();
        sh[t] += v;
        __syncthreads();
    }
    int ex = sh[t] - pair + base;
    if (i0 < NN) {
        g_rowstart[i0] = ex;
        g_fill[i0] = ex;
    }
    if (i0 + 1 < NN) {
        g_rowstart[i0 + 1] = ex + c0;
        g_fill[i0 + 1] = ex + c0;
    }
}

__global__ void fill_kernel(const int* __restrict__ ei) {
    int e = blockIdx.x * blockDim.x + threadIdx.x;
    if (e >= EE) return;
    int r = __ldg(&ei[e]);
    int c = __ldg(&ei[EE + e]);
    int pos = atomicAdd(&g_fill[c], 1);
    g_csr_r[pos] = r;
}

// ---------------- mm0: proven R10 version (unchanged) ----------------
#define MMB 256
#define MMG ((NN + MMB - 1) / MMB)      // 391
__global__ __launch_bounds__(128, 3) void mm0_kernel(const float* __restrict__ x,
                                                     const float* __restrict__ W) {
    __shared__ __align__(16) float Ws[FIN * HID];      // 32 KB
    __shared__ __align__(16) float xs[2][MMB * 16];    // 32 KB
    int tid = threadIdx.x;
    for (int i = tid; i < FIN * HID; i += 128) Ws[i] = W[i];

    int n0 = blockIdx.x * MMB;
    int lr = tid >> 2;
    int cb = tid & 3;

    auto issue_chunk = [&](int kc, int b) {
#pragma unroll
        for (int it = 0; it < 8; it++) {
            int r = it * 32 + lr;
            int gr = n0 + r;
            if (gr >= NN) gr = NN - 1;
            const float* src = &x[(size_t)gr * FIN + kc * 16 + cb * 4];
            int blk = cb ^ ((r >> 1) & 3);
            unsigned sdst = (unsigned)__cvta_generic_to_shared(&xs[b][r * 16 + blk * 4]);
            asm volatile("cp.async.cg.shared.global [%0], [%1], 16;"
                         :: "r"(sdst), "l"(src));
        }
        asm volatile("cp.async.commit_group;");
    };

    issue_chunk(0, 0);
    issue_chunk(1, 1);

    unsigned long long accA[8], accB[8];
#pragma unroll
    for (int p = 0; p < 8; p++) { accA[p] = 0ull; accB[p] = 0ull; }

    int r0 = tid;
    int r1 = tid + 128;
    int key = (tid >> 1) & 3;

    for (int kc = 0; kc < FIN / 16; kc++) {
        if (kc < FIN / 16 - 1)
            asm volatile("cp.async.wait_group 1;");
        else
            asm volatile("cp.async.wait_group 0;");
        __syncthreads();

        const float4* base = (const float4*)&xs[kc & 1][0];
#pragma unroll
        for (int c = 0; c < 4; c++) {
            float4 va = base[r0 * 4 + (c ^ key)];
            float4 vb = base[r1 * 4 + (c ^ key)];
            float xa[4] = {va.x, va.y, va.z, va.w};
            float xb[4] = {vb.x, vb.y, vb.z, vb.w};
#pragma unroll
            for (int kk = 0; kk < 4; kk++) {
                int k = kc * 16 + c * 4 + kk;
                const ulonglong2* wp = (const ulonglong2*)&Ws[k * HID];
                ulonglong2 w01 = wp[0], w23 = wp[1], w45 = wp[2], w67 = wp[3];
                unsigned long long xpA = pack2(xa[kk]);
                unsigned long long xpB = pack2(xb[kk]);
                fma2(accA[0], xpA, w01.x); fma2(accA[1], xpA, w01.y);
                fma2(accA[2], xpA, w23.x); fma2(accA[3], xpA, w23.y);
                fma2(accA[4], xpA, w45.x); fma2(accA[5], xpA, w45.y);
                fma2(accA[6], xpA, w67.x); fma2(accA[7], xpA, w67.y);
                fma2(accB[0], xpB, w01.x); fma2(accB[1], xpB, w01.y);
                fma2(accB[2], xpB, w23.x); fma2(accB[3], xpB, w23.y);
                fma2(accB[4], xpB, w45.x); fma2(accB[5], xpB, w45.y);
                fma2(accB[6], xpB, w67.x); fma2(accB[7], xpB, w67.y);
            }
        }
        __syncthreads();
        if (kc + 2 < FIN / 16) issue_chunk(kc + 2, kc & 1);
    }

    union { unsigned long long u; float2 f; } cv;
    int nA = n0 + r0;
    if (nA < NN) {
        float dv = g_deg[nA];
        float4* o = (float4*)&g_h[(size_t)nA * HID];
#pragma unroll
        for (int q = 0; q < 4; q++) {
            float4 rr;
            cv.u = accA[2 * q];     rr.x = cv.f.x * dv; rr.y = cv.f.y * dv;
            cv.u = accA[2 * q + 1]; rr.z = cv.f.x * dv; rr.w = cv.f.y * dv;
            o[q] = rr;
        }
    }
    int nB = n0 + r1;
    if (nB < NN) {
        float dv = g_deg[nB];
        float4* o = (float4*)&g_h[(size_t)nB * HID];
#pragma unroll
        for (int q = 0; q < 4; q++) {
            float4 rr;
            cv.u = accB[2 * q];     rr.x = cv.f.x * dv; rr.y = cv.f.y * dv;
            cv.u = accB[2 * q + 1]; rr.z = cv.f.x * dv; rr.w = cv.f.y * dv;
            o[q] = rr;
        }
    }
}

// ---------------- gather: warp per node, 4 lanes/edge, 2-way unroll (proven) ----------------
__global__ __launch_bounds__(256) void gather_kernel() {
    int node = blockIdx.x * 8 + (threadIdx.x >> 5);
    if (node >= NN) return;
    int lane = threadIdx.x & 31;
    int p = lane & 3;

    int s = g_rowstart[node];
    int e = s + g_cnt[node];
    int j = s + (lane >> 2);

    float4 a0 = make_float4(0.f, 0.f, 0.f, 0.f);
    float4 a1 = make_float4(0.f, 0.f, 0.f, 0.f);
    const float4* h4 = (const float4*)g_h;

    while (j < e - 8) {
        int r0 = __ldg(&g_csr_r[j]);
        int r1 = __ldg(&g_csr_r[j + 8]);
        float4 v0 = __ldg(&h4[(size_t)r0 * 4 + p]);
        float4 v1 = __ldg(&h4[(size_t)r1 * 4 + p]);
        a0.x += v0.x; a0.y += v0.y; a0.z += v0.z; a0.w += v0.w;
        a1.x += v1.x; a1.y += v1.y; a1.z += v1.z; a1.w += v1.w;
        j += 16;
    }
    if (j < e) {
        int r0 = __ldg(&g_csr_r[j]);
        float4 v0 = __ldg(&h4[(size_t)r0 * 4 + p]);
        a0.x += v0.x; a0.y += v0.y; a0.z += v0.z; a0.w += v0.w;
    }
    a0.x += a1.x; a0.y += a1.y; a0.z += a1.z; a0.w += a1.w;

#pragma unroll
    for (int m = 16; m >= 4; m >>= 1) {
        a0.x += __shfl_xor_sync(0xffffffff, a0.x, m);
        a0.y += __shfl_xor_sync(0xffffffff, a0.y, m);
        a0.z += __shfl_xor_sync(0xffffffff, a0.z, m);
        a0.w += __shfl_xor_sync(0xffffffff, a0.w, m);
    }
    if (lane < 4) {
        float dc = g_deg[node];
        a0.x *= dc; a0.y *= dc; a0.z *= dc; a0.w *= dc;
        ((float4*)g_agg)[(size_t)node * 4 + lane] = a0;
    }
}

// ---------------- fused stats + grid-sync + apply (+mm16 / out) ----------------
// Single wave guaranteed: 391 blocks, __launch_bounds__(256,3) -> >=3 blocks/SM
// (444 slots >= 391). Last-block finalize releases g_flag=epoch; all blocks
// spin-wait then run apply with xr/sv still in registers.
__global__ __launch_bounds__(256, 3) void statsapply_kernel(
    const float* __restrict__ L, const float* __restrict__ gamma,
    const float* __restrict__ beta, const float* __restrict__ Wn,
    float* __restrict__ out, int epoch, int isfinal)
{
    __shared__ float Ls[HID * NG];
    __shared__ float xs[256 * HID];
    __shared__ float ss[256 * NG];
    __shared__ float tsh[GF];
    __shared__ float rgS[GF];
    __shared__ float csS[HID];
    __shared__ float WsS[HID * HID];
    __shared__ int is_last;
    int tid = threadIdx.x;
    if (tid < HID * NG) Ls[tid] = L[tid];
    __syncthreads();

    int nIdx = blockIdx.x * 256 + tid;
    float xr[HID];
    float sv[NG];
#pragma unroll
    for (int k = 0; k < HID; k++) xr[k] = 0.0f;
#pragma unroll
    for (int g = 0; g < NG; g++) sv[g] = 0.0f;

    if (nIdx < NN) {
        const float4* xi = (const float4*)&g_agg[(size_t)nIdx * HID];
#pragma unroll
        for (int q = 0; q < 4; q++) {
            float4 v = xi[q];
            xr[q * 4 + 0] = v.x; xr[q * 4 + 1] = v.y; xr[q * 4 + 2] = v.z; xr[q * 4 + 3] = v.w;
        }
        float logit[NG];
#pragma unroll
        for (int g = 0; g < NG; g++) logit[g] = 0.0f;
#pragma unroll
        for (int k = 0; k < HID; k++)
#pragma unroll
            for (int g = 0; g < NG; g++) logit[g] += xr[k] * Ls[k * NG + g];
        float m = -CUDART_INF_F;
#pragma unroll
        for (int g = 0; g < NG; g++) m = fmaxf(m, logit[g]);
        float sum = 0.0f;
#pragma unroll
        for (int g = 0; g < NG; g++) { sv[g] = __expf(logit[g] - m); sum += sv[g]; }
        float inv = 1.0f / sum;
#pragma unroll
        for (int g = 0; g < NG; g++) sv[g] *= inv;
    }

    {
        float4* xw = (float4*)&xs[tid * HID];
#pragma unroll
        for (int q = 0; q < 4; q++)
            xw[q] = make_float4(xr[q * 4 + 0], xr[q * 4 + 1], xr[q * 4 + 2], xr[q * 4 + 3]);
#pragma unroll
        for (int g = 0; g < NG; g++) ss[tid * NG + g] = sv[g];
    }
    __syncthreads();

    if (tid < GF) {
        int g = tid >> 4;
        int f = tid & 15;
        float a1 = 0.0f, a2 = 0.0f;
        for (int jj = 0; jj < 256; jj++) {
            float t = ss[jj * NG + g] * xs[jj * HID + f];
            a1 += t;
            a2 += t * t;
        }
        atomicAdd(&g_sums[tid], (double)a1);
        atomicAdd(&g_sums[GF + tid], (double)a2);
    }

    // -------- decoupled finalize --------
    __threadfence();
    if (tid == 0) {
        int old = atomicAdd(&g_ctr, 1);
        is_last = (old == (int)gridDim.x - 1) ? 1 : 0;
    }
    __syncthreads();
    if (is_last) {
        if (tid < GF) {
            double s1 = g_sums[tid];
            double s2 = g_sums[GF + tid];
            g_sums[tid] = 0.0;
            g_sums[GF + tid] = 0.0;
            double mean = s1 / (double)NN;
            double var  = s2 / (double)NN - mean * mean;
            float v = (float)var;
            if (v < 0.0f) v = 0.0f;
            float rs = rsqrtf(v + EPSN);
            float rg = rs * gamma[tid];
            g_rsg[tid] = rg;
            tsh[tid] = beta[tid] - (float)mean * rg;
        }
        __syncthreads();
        if (tid < HID) {
            float cf = 0.0f;
#pragma unroll
            for (int g = 0; g < NG; g++) cf += tsh[g * HID + tid];
            g_cvec[tid] = cf;
        }
        if (tid == 0) g_ctr = 0;
        __syncthreads();
        if (tid == 0) {
            __threadfence();                    // release rsg/cvec
            atomicExch((int*)&g_flag, epoch);
        }
    }

    // -------- grid sync: wait for BN constants --------
    if (tid == 0) {
        while (atomicAdd((int*)&g_flag, 0) != epoch) __nanosleep(64);
    }
    __syncthreads();

    if (tid < GF) rgS[tid] = __ldcg(&g_rsg[tid]);
    if (tid < HID) csS[tid] = __ldcg(&g_cvec[tid]);
    if (!isfinal && tid < HID * HID) WsS[tid] = Wn[tid];
    __syncthreads();

    // -------- apply (+mm16 or final output) --------
    if (nIdx < NN) {
        float res[HID];
#pragma unroll
        for (int f = 0; f < HID; f++) {
            float a = 0.0f;
#pragma unroll
            for (int g = 0; g < NG; g++) a += sv[g] * rgS[g * HID + f];
            float v = xr[f] + LAMDA * (xr[f] * a + csS[f]);
            res[f] = fmaxf(v, 0.0f);
        }

        if (isfinal) {
            float4* o = (float4*)&out[(size_t)nIdx * HID];
#pragma unroll
            for (int q = 0; q < 4; q++)
                o[q] = make_float4(res[q * 4 + 0], res[q * 4 + 1],
                                   res[q * 4 + 2], res[q * 4 + 3]);
        } else {
            float acc[HID];
#pragma unroll
            for (int f = 0; f < HID; f++) acc[f] = 0.0f;
#pragma unroll
            for (int k = 0; k < HID; k++)
#pragma unroll
                for (int f = 0; f < HID; f++) acc[f] += res[k] * WsS[k * HID + f];
            float dv = g_deg[nIdx];
            float4* o = (float4*)&g_h[(size_t)nIdx * HID];
#pragma unroll
            for (int q = 0; q < 4; q++)
                o[q] = make_float4(acc[q * 4 + 0] * dv, acc[q * 4 + 1] * dv,
                                   acc[q * 4 + 2] * dv, acc[q * 4 + 3] * dv);
        }
    }

    // -------- reset flag for next layer / replay --------
    __threadfence();
    if (tid == 0) {
        int old = atomicAdd(&g_ctr2, 1);
        if (old == (int)gridDim.x - 1) {
            g_ctr2 = 0;
            atomicExch((int*)&g_flag, 0);
        }
    }
}

// ---------------- launcher ----------------
extern "C" void kernel_launch(void* const* d_in, const int* in_sizes, int n_in,
                              void* d_out, int out_size) {
    const float* x  = (const float*)d_in[0];
    const int*   ei = (const int*)d_in[1];
    const float* W[3] = {(const float*)d_in[2], (const float*)d_in[3], (const float*)d_in[4]};
    const float* L[3] = {(const float*)d_in[5], (const float*)d_in[6], (const float*)d_in[7]};
    const float* gm[3] = {(const float*)d_in[8], (const float*)d_in[9], (const float*)d_in[10]};
    const float* bt[3] = {(const float*)d_in[11], (const float*)d_in[12], (const float*)d_in[13]};
    float* out = (float*)d_out;

    const int TB = 256;
    zero_cnt_kernel<<<(NN + TB - 1) / TB, TB>>>();        // 1
    count_kernel<<<(EE + TB - 1) / TB, TB>>>(ei);         // 2
    scan1_kernel<<<NBLK, 512>>>();                        // 3 (+dinv fused)
    mm0_kernel<<<MMG, 128>>>(x, W[0]);                    // 4  <- profiled slot
    scan3_kernel<<<NBLK, 512>>>();                        // 5
    fill_kernel<<<(EE + TB - 1) / TB, TB>>>(ei);          // 6

    for (int i = 0; i < 3; i++) {
        gather_kernel<<<(NN + 7) / 8, 256>>>();
        statsapply_kernel<<<(NN + 255) / 256, 256>>>(
            L[i], gm[i], bt[i], i < 2 ? W[i + 1] : W[0], out, i + 1, i == 2 ? 1 : 0);
    }
}